// round 16
// baseline (speedup 1.0000x reference)
#include <cuda_runtime.h>
#include <math.h>
#include <stdint.h>

#define BATCH 8
#define NCIN 8
#define HID 64
#define LNK 9
#define HH 120
#define WW 120
#define HW (HH*WW)      // 14400
#define C3 (3*HID)      // 192

__device__ __forceinline__ uint32_t f2tf32(float v) {
    uint32_t r; asm("cvt.rna.tf32.f32 %0, %1;" : "=r"(r) : "f"(v)); return r;
}
__device__ __forceinline__ void mma_tf32(float* d,
    uint32_t a0, uint32_t a1, uint32_t a2, uint32_t a3,
    uint32_t b0, uint32_t b1)
{
    asm volatile("mma.sync.aligned.m16n8k8.row.col.f32.tf32.tf32.f32 "
        "{%0,%1,%2,%3}, {%4,%5,%6,%7}, {%8,%9}, {%0,%1,%2,%3};"
        : "+f"(d[0]), "+f"(d[1]), "+f"(d[2]), "+f"(d[3])
        : "r"(a0), "r"(a1), "r"(a2), "r"(a3), "r"(b0), "r"(b1));
}
__device__ __forceinline__ float fsigmoid(float x) {
    return 1.f / (1.f + __expf(-x));
}
__device__ __forceinline__ float ftanh(float x) {
    return 1.f - 2.f / (1.f + __expf(2.f*x));
}
__device__ __forceinline__ int kslot(int k) {
    return (k & ~7) + ((k >> 2) & 1) + 2*(k & 3);
}

// -------- scratch (device globals) ----------------------------------------
__device__ float    g_flows[BATCH*2*LNK*HW];
__device__ float    g_i2h[(size_t)BATCH*C3*HW];
__device__ float4   g_hT4[(size_t)BATCH*HW*16];    // h_prev [b][p][64] fp32 slot-permuted
__device__ uint32_t g_xhT[(size_t)BATCH*HW*72];    // [b][p][72] tf32 permuted
__device__ uint32_t g_xT[(size_t)BATCH*HW*8];      // x only, dense [b][p][8] tf32 permuted
__device__ uint32_t g_fT[(size_t)BATCH*HW*32];     // f [b][p][32] tf32 permuted
__device__ uint32_t g_wf[25*32*72];
__device__ uint32_t g_wB[LNK*192*64];
__device__ uint32_t g_wI[192*72];
__device__ uint32_t g_wFl[25*24*32];

// ---------------- transpose h_prev (+x) -> permuted channels-last ----------
__global__ void k_transpose(const float* __restrict__ hp, const float* __restrict__ x)
{
    __shared__ float t[32][33];
    int b  = blockIdx.z;
    int c0 = blockIdx.y * 32;
    int p0 = blockIdx.x * 32;
    int tx = threadIdx.x, ty = threadIdx.y;
    float* hT = (float*)g_hT4;
#pragma unroll
    for (int k = 0; k < 4; k++) {
        int c = c0 + ty + k*8;
        t[ty + k*8][tx] = hp[((size_t)b*HID + c)*HW + p0 + tx];
    }
    if (blockIdx.y == 0) {
        float vx = x[((size_t)b*NCIN + ty)*HW + p0 + tx];
        uint32_t bits = f2tf32(vx);
        int slot = kslot(ty);
        g_xhT[((size_t)b*HW + p0 + tx)*72 + slot] = bits;
        g_xT [((size_t)b*HW + p0 + tx)*8  + slot] = bits;
    }
    __syncthreads();
    int c = c0 + tx;
    int slot = kslot(c);
#pragma unroll
    for (int k = 0; k < 4; k++) {
        int p = p0 + ty + k*8;
        float v = t[tx][ty + k*8];
        hT[((size_t)b*HW + p)*HID + slot] = v;
        g_xhT[((size_t)b*HW + p)*72 + 8 + slot] = f2tf32(v);
    }
}

// ---------------- merged weight prep ---------------------------------------
#define NW_F  (25*32*72)
#define NW_B  (LNK*192*64)
#define NW_I  (192*72)
#define NW_FL (25*24*32)
#define NW_ALL (NW_F + NW_B + NW_I + NW_FL)

__global__ void k_prep_all(
    const float* __restrict__ i2f_w, const float* __restrict__ h2f_w,
    const float* __restrict__ h2h_w, const float* __restrict__ i2h_w,
    const float* __restrict__ flows_w)
{
    int idx = blockIdx.x*256 + threadIdx.x;
    if (idx < NW_F) {
        int t  = idx / (32*72);
        int r  = idx % (32*72);
        int oc = r / 72, k = r % 72;
        float v = (k < 8) ? i2f_w[((size_t)oc*NCIN + k)*25 + t]
                          : h2f_w[((size_t)oc*HID + (k-8))*25 + t];
        g_wf[t*(32*72) + oc*72 + kslot(k)] = f2tf32(v);
        return;
    }
    idx -= NW_F;
    if (idx < NW_B) {
        int l = idx / (192*64);
        int r = idx % (192*64);
        int o = r / 64, p = r % 64;
        int k = (p & ~7) + ((p & 1) << 2) + ((p & 7) >> 1);
        g_wB[idx] = f2tf32(h2h_w[(size_t)o*576 + l*64 + k]);
        return;
    }
    idx -= NW_B;
    if (idx < NW_I) {
        int o = idx / 72, p = idx % 72;
        int t = p >> 3, q = p & 7;
        int c = ((q & 1) << 2) + (q >> 1);
        g_wI[idx] = f2tf32(i2h_w[(size_t)o*72 + c*9 + t]);
        return;
    }
    idx -= NW_I;
    if (idx < NW_FL) {
        int t = idx / (24*32);
        int r = idx % (24*32);
        int o = r / 32, p = r % 32;
        int c = (p & ~7) + ((p & 1) << 2) + ((p & 7) >> 1);
        uint32_t v = 0u;
        if (o < 18) v = f2tf32(flows_w[(size_t)o*(32*25) + c*25 + t]);
        g_wFl[t*(24*32) + o*32 + p] = v;
    }
}

// ==========================================================================
// k_f_mma: f = relu(conv5x5(xh; wf)) -> g_fT
// ==========================================================================
#define KF_AS 76
#define KF_AROWS 132
#define KF_OFF_B (KF_AROWS*KF_AS*4)
#define KF_SMEM  (KF_OFF_B + 160*KF_AS*4)

__global__ __launch_bounds__(256, 2) void k_f_mma(
    const float* __restrict__ i2f_b, const float* __restrict__ h2f_b)
{
    extern __shared__ char sm[];
    uint32_t* sA = (uint32_t*)sm;
    uint32_t* sB = (uint32_t*)(sm + KF_OFF_B);

    int b   = blockIdx.y;
    int y0  = blockIdx.x;
    int tid = threadIdx.x;
    int wid = tid >> 5, lane = tid & 31;
    int warpM = wid & 3, warpN = wid >> 2;
    int lq = lane >> 2, lr = lane & 3;

    float acc[2][2][4];
#pragma unroll
    for (int mi = 0; mi < 2; mi++)
#pragma unroll
        for (int ni = 0; ni < 2; ni++)
#pragma unroll
            for (int j = 0; j < 4; j++) acc[mi][ni][j] = 0.f;

    for (int i = tid; i < 8*KF_AS; i += 256)
        sA[124*KF_AS + i] = 0;

    const uint4* xh4 = (const uint4*)(g_xhT + (size_t)b*HW*72);

    for (int dy = 0; dy < 5; dy++) {
        __syncthreads();
        int iy = y0 + dy - 2;
        for (int idx = tid; idx < 124*18; idx += 256) {
            int col = idx / 18, kq = idx % 18;
            int gx = col - 2;
            uint4 v = make_uint4(0u, 0u, 0u, 0u);
            if (iy >= 0 && iy < HH && gx >= 0 && gx < WW)
                v = xh4[((size_t)iy*WW + gx)*18 + kq];
            *(uint4*)&sA[col*KF_AS + kq*4] = v;
        }
        const uint4* wsrc = (const uint4*)&g_wf[dy*5*(32*72)];
        for (int idx = tid; idx < 5*32*18; idx += 256) {
            int row = idx / 18, kq = idx % 18;
            *(uint4*)&sB[row*KF_AS + kq*4] = wsrc[row*18 + kq];
        }
        __syncthreads();

#pragma unroll
        for (int dx = 0; dx < 5; dx++) {
            const uint32_t* Ab = sA + (warpM*32 + dx + lq)*KF_AS;
            const uint32_t* Bb = sB + (dx*32 + warpN*16 + lq)*KF_AS;
#pragma unroll
            for (int kb = 0; kb < 9; kb++) {
                int col = kb*8 + 2*lr;
                uint2 a00 = *(const uint2*)&Ab[col];
                uint2 a01 = *(const uint2*)&Ab[ 8*KF_AS + col];
                uint2 a10 = *(const uint2*)&Ab[16*KF_AS + col];
                uint2 a11 = *(const uint2*)&Ab[24*KF_AS + col];
                uint2 b0  = *(const uint2*)&Bb[col];
                uint2 b1  = *(const uint2*)&Bb[ 8*KF_AS + col];
                mma_tf32(acc[0][0], a00.x, a01.x, a00.y, a01.y, b0.x, b0.y);
                mma_tf32(acc[0][1], a00.x, a01.x, a00.y, a01.y, b1.x, b1.y);
                mma_tf32(acc[1][0], a10.x, a11.x, a10.y, a11.y, b0.x, b0.y);
                mma_tf32(acc[1][1], a10.x, a11.x, a10.y, a11.y, b1.x, b1.y);
            }
        }
    }

    __syncthreads();
#pragma unroll
    for (int ni = 0; ni < 2; ni++) {
        int ocA = warpN*16 + ni*8 + 2*lr, ocB = ocA + 1;
        int sA_ = kslot(ocA), sB_ = kslot(ocB);
        float bA = __ldg(&i2f_b[ocA]) + __ldg(&h2f_b[ocA]);
        float bB = __ldg(&i2f_b[ocB]) + __ldg(&h2f_b[ocB]);
#pragma unroll
        for (int mi = 0; mi < 2; mi++) {
            int x0 = warpM*32 + mi*16 + lq;
            int x1 = x0 + 8;
            sA[x0*32 + sA_] = f2tf32(fmaxf(acc[mi][ni][0] + bA, 0.f));
            sA[x0*32 + sB_] = f2tf32(fmaxf(acc[mi][ni][1] + bB, 0.f));
            sA[x1*32 + sA_] = f2tf32(fmaxf(acc[mi][ni][2] + bA, 0.f));
            sA[x1*32 + sB_] = f2tf32(fmaxf(acc[mi][ni][3] + bB, 0.f));
        }
    }
    __syncthreads();
    uint4* fT4 = (uint4*)(g_fT + ((size_t)b*HW + (size_t)y0*WW)*32);
    for (int idx = tid; idx < 120*8; idx += 256)
        fT4[idx] = ((const uint4*)sA)[idx];
}

// ==========================================================================
// k_flows_mma: flows = conv5x5(f; wFl)
// ==========================================================================
#define KFL_AS 36
__global__ __launch_bounds__(256, 2) void k_flows_mma(const float* __restrict__ flows_b)
{
    __shared__ uint32_t sA[KF_AROWS*KFL_AS];
    __shared__ uint32_t sB[120*KFL_AS];

    int b   = blockIdx.y;
    int y0  = blockIdx.x;
    int tid = threadIdx.x;
    int wid = tid >> 5, lane = tid & 31;
    int lq = lane >> 2, lr = lane & 3;

    float acc[3][4];
#pragma unroll
    for (int ni = 0; ni < 3; ni++)
#pragma unroll
        for (int j = 0; j < 4; j++) acc[ni][j] = 0.f;

    for (int i = tid; i < 8*KFL_AS; i += 256)
        sA[124*KFL_AS + i] = 0;

    const uint4* fT4 = (const uint4*)(g_fT + (size_t)b*HW*32);

    for (int dy = 0; dy < 5; dy++) {
        __syncthreads();
        int iy = y0 + dy - 2;
        for (int idx = tid; idx < 124*8; idx += 256) {
            int col = idx >> 3, kq = idx & 7;
            int gx = col - 2;
            uint4 v = make_uint4(0u, 0u, 0u, 0u);
            if (iy >= 0 && iy < HH && gx >= 0 && gx < WW)
                v = fT4[((size_t)iy*WW + gx)*8 + kq];
            *(uint4*)&sA[col*KFL_AS + kq*4] = v;
        }
        const uint4* wsrc = (const uint4*)&g_wFl[dy*5*(24*32)];
        for (int idx = tid; idx < 5*24*8; idx += 256) {
            int row = idx >> 3, kq = idx & 7;
            *(uint4*)&sB[row*KFL_AS + kq*4] = wsrc[idx];
        }
        __syncthreads();

#pragma unroll
        for (int dx = 0; dx < 5; dx++) {
            const uint32_t* Ab = sA + (wid*16 + dx + lq)*KFL_AS;
            const uint32_t* Bb = sB + (dx*24 + lq)*KFL_AS;
#pragma unroll
            for (int kb = 0; kb < 4; kb++) {
                int col = kb*8 + 2*lr;
                uint2 a0 = *(const uint2*)&Ab[col];
                uint2 a1 = *(const uint2*)&Ab[8*KFL_AS + col];
#pragma unroll
                for (int ni = 0; ni < 3; ni++) {
                    uint2 bb = *(const uint2*)&Bb[ni*8*KFL_AS + col];
                    mma_tf32(acc[ni], a0.x, a1.x, a0.y, a1.y, bb.x, bb.y);
                }
            }
        }
    }

    int x0 = wid*16 + lq, x1 = x0 + 8;
#pragma unroll
    for (int ni = 0; ni < 3; ni++) {
        int ocA = ni*8 + 2*lr, ocB = ocA + 1;
        if (ocA < 18) {
            float bias = __ldg(&flows_b[ocA]);
            float* o = &g_flows[((size_t)b*(2*LNK) + ocA)*HW + (size_t)y0*WW];
            if (x0 < WW) o[x0] = acc[ni][0] + bias;
            if (x1 < WW) o[x1] = acc[ni][2] + bias;
        }
        if (ocB < 18) {
            float bias = __ldg(&flows_b[ocB]);
            float* o = &g_flows[((size_t)b*(2*LNK) + ocB)*HW + (size_t)y0*WW];
            if (x0 < WW) o[x0] = acc[ni][1] + bias;
            if (x1 < WW) o[x1] = acc[ni][3] + bias;
        }
    }
}

// ==========================================================================
// k_i2h_mma: i2h = conv3x3(x) full 192 oc, NCHW out; taps from dense g_xT
// ==========================================================================
#define KI_AS 76
#define KI_OFF_B (128*KI_AS*4)
#define KI_SMEM  (KI_OFF_B + 192*KI_AS*4)

__global__ __launch_bounds__(256, 2) void k_i2h_mma(const float* __restrict__ i2h_b)
{
    extern __shared__ char sm[];
    uint32_t* sA = (uint32_t*)sm;
    uint32_t* sB = (uint32_t*)(sm + KI_OFF_B);

    int b   = blockIdx.y;
    int y0  = blockIdx.x;
    int tid = threadIdx.x;
    int wid = tid >> 5, lane = tid & 31;
    int warpM = wid & 3, warpN = wid >> 2;
    int lq = lane >> 2, lr = lane & 3;

    const uint4* xT4 = (const uint4*)(g_xT + (size_t)b*HW*8);

    for (int idx = tid; idx < 128*18; idx += 256) {
        int px = idx / 18, r = idx % 18;
        int t = r >> 1, half = r & 1;
        int dy = t / 3, dx = t % 3;
        int iy = y0 + dy - 1, gx = px + dx - 1;
        uint4 v = make_uint4(0u, 0u, 0u, 0u);
        if (iy >= 0 && iy < HH && gx >= 0 && gx < WW)
            v = xT4[((size_t)iy*WW + gx)*2 + half];
        *(uint4*)&sA[px*KI_AS + t*8 + half*4] = v;
    }
    {
        const uint4* wI4 = (const uint4*)g_wI;
        for (int idx = tid; idx < 192*18; idx += 256) {
            int o = idx / 18, kq = idx % 18;
            *(uint4*)&sB[o*KI_AS + kq*4] = wI4[idx];
        }
    }
    __syncthreads();

    float acc[2][12][4];
#pragma unroll
    for (int mi = 0; mi < 2; mi++)
#pragma unroll
        for (int ni = 0; ni < 12; ni++)
#pragma unroll
            for (int j = 0; j < 4; j++) acc[mi][ni][j] = 0.f;

    const uint32_t* Ab = sA + (warpM*32 + lq)*KI_AS;
    const uint32_t* Bb = sB + (warpN*96 + lq)*KI_AS;
#pragma unroll
    for (int kb = 0; kb < 9; kb++) {
        int col = kb*8 + 2*lr;
        uint2 a00 = *(const uint2*)&Ab[col];
        uint2 a01 = *(const uint2*)&Ab[ 8*KI_AS + col];
        uint2 a10 = *(const uint2*)&Ab[16*KI_AS + col];
        uint2 a11 = *(const uint2*)&Ab[24*KI_AS + col];
#pragma unroll
        for (int ni = 0; ni < 12; ni++) {
            uint2 bb = *(const uint2*)&Bb[ni*8*KI_AS + col];
            mma_tf32(acc[0][ni], a00.x, a01.x, a00.y, a01.y, bb.x, bb.y);
            mma_tf32(acc[1][ni], a10.x, a11.x, a10.y, a11.y, bb.x, bb.y);
        }
    }

#pragma unroll
    for (int ni = 0; ni < 12; ni++) {
        int ocA = warpN*96 + ni*8 + 2*lr, ocB = ocA + 1;
        float bA = __ldg(&i2h_b[ocA]);
        float bB = __ldg(&i2h_b[ocB]);
        float* oA = &g_i2h[((size_t)b*C3 + ocA)*HW + (size_t)y0*WW];
        float* oB = &g_i2h[((size_t)b*C3 + ocB)*HW + (size_t)y0*WW];
#pragma unroll
        for (int mi = 0; mi < 2; mi++) {
            int x0 = warpM*32 + mi*16 + lq;
            int x1 = x0 + 8;
            if (x0 < WW) {
                oA[x0] = acc[mi][ni][0] + bA;
                oB[x0] = acc[mi][ni][1] + bB;
            }
            if (x1 < WW) {
                oA[x1] = acc[mi][ni][2] + bA;
                oB[x1] = acc[mi][ni][3] + bB;
            }
        }
    }
}

// ==========================================================================
// k_main: warp(x9) + 1x1 conv + GRU gates. R10 structure with ONE change:
// per link, threads <128 compute geometry while threads >=128 stage all
// of B concurrently (was: geo half-idle, then stageB serialized).
// ==========================================================================
#define SA_STRIDE 72
#define SB_STRIDE 72
#define OFF_GEO 0
#define OFF_A   4096
#define OFF_B   (OFF_A + 128*SA_STRIDE*4)
#define PHASE1_BYTES (OFF_B + 192*SB_STRIDE*4)
#define SD_STRIDE 194
#define SD_BYTES (128*SD_STRIDE*4)
#define SMEM_MMA_BYTES (SD_BYTES > PHASE1_BYTES ? SD_BYTES : PHASE1_BYTES)

__global__ __launch_bounds__(256, 2) void k_main_mma(
    const float* __restrict__ hp,
    const float* __restrict__ h2h_b,
    float* __restrict__ out)
{
    extern __shared__ char sm[];
    float*    sgeo = (float*)(sm + OFF_GEO);
    uint32_t* sA   = (uint32_t*)(sm + OFF_A);
    uint32_t* sB   = (uint32_t*)(sm + OFF_B);
    float*    sD   = (float*)sm;

    int b   = blockIdx.y;
    int p0  = blockIdx.x * 128;
    int tid = threadIdx.x;
    int wid = tid >> 5, lane = tid & 31;
    int warpM = wid & 3, warpN = wid >> 2;
    int lq = lane >> 2, lr = lane & 3;

    float acc[2][12][4];
#pragma unroll
    for (int mi = 0; mi < 2; mi++)
#pragma unroll
        for (int ni = 0; ni < 12; ni++)
#pragma unroll
            for (int j = 0; j < 4; j++) acc[mi][ni][j] = 0.f;

    const float4* hT4 = g_hT4 + (size_t)b*HW*16;

    for (int l = 0; l < LNK; l++) {
        if (tid < 128) {
            // geometry for this link (128 px)
            int p = p0 + tid; if (p > HW-1) p = HW-1;
            int yc = p / WW, xc = p - yc*WW;
            float sx = (float)xc + g_flows[((size_t)b*(2*LNK) + 2*l    )*HW + p];
            float sy = (float)yc + g_flows[((size_t)b*(2*LNK) + 2*l + 1)*HW + p];
            float fx = floorf(sx), fy = floorf(sy);
            float wx1 = sx - fx, wy1 = sy - fy;
            float wx0 = 1.f - wx1, wy0 = 1.f - wy1;
            int ix0 = (int)fx, iy0 = (int)fy;
            bool vx0 = (ix0 >= 0) && (ix0 < WW);
            bool vx1 = (ix0 >= -1) && (ix0 < WW - 1);
            bool vy0 = (iy0 >= 0) && (iy0 < HH);
            bool vy1 = (iy0 >= -1) && (iy0 < HH - 1);
            int r0 = iy0*WW, r1 = r0 + WW;
            float* g = &sgeo[tid*8];
            g[0] = wy0*wx0; g[1] = wy0*wx1; g[2] = wy1*wx0; g[3] = wy1*wx1;
            ((int*)g)[4] = (vy0 && vx0) ? (r0 + ix0)     : -1;
            ((int*)g)[5] = (vy0 && vx1) ? (r0 + ix0 + 1) : -1;
            ((int*)g)[6] = (vy1 && vx0) ? (r1 + ix0)     : -1;
            ((int*)g)[7] = (vy1 && vx1) ? (r1 + ix0 + 1) : -1;
        } else {
            // stage all of B concurrently (3072 uint4s over 128 threads)
            const uint4* wB4 = (const uint4*)&g_wB[(size_t)l*192*64];
            int t2 = tid - 128;
#pragma unroll
            for (int i = 0; i < 24; i++) {
                int q = i*128 + t2;
                int o = q >> 4, kq = q & 15;
                *(uint4*)&sB[o*SB_STRIDE + kq*4] = wB4[o*16 + kq];
            }
        }
        __syncthreads();

        // gather A (all threads)
#pragma unroll
        for (int i = 0; i < 8; i++) {
            int item = i*256 + tid;
            int px = item >> 4, cg = item & 15;
            const float* g = &sgeo[px*8];
            float w00 = g[0], w01 = g[1], w10 = g[2], w11 = g[3];
            int i00 = ((const int*)g)[4], i01 = ((const int*)g)[5];
            int i10 = ((const int*)g)[6], i11 = ((const int*)g)[7];
            float ax=0.f, ay=0.f, az=0.f, aw=0.f;
            if (i00 >= 0) { float4 v = hT4[(size_t)i00*16 + cg];
                ax += w00*v.x; ay += w00*v.y; az += w00*v.z; aw += w00*v.w; }
            if (i01 >= 0) { float4 v = hT4[(size_t)i01*16 + cg];
                ax += w01*v.x; ay += w01*v.y; az += w01*v.z; aw += w01*v.w; }
            if (i10 >= 0) { float4 v = hT4[(size_t)i10*16 + cg];
                ax += w10*v.x; ay += w10*v.y; az += w10*v.z; aw += w10*v.w; }
            if (i11 >= 0) { float4 v = hT4[(size_t)i11*16 + cg];
                ax += w11*v.x; ay += w11*v.y; az += w11*v.z; aw += w11*v.w; }
            uint4 t;
            t.x = f2tf32(ax); t.y = f2tf32(ay); t.z = f2tf32(az); t.w = f2tf32(aw);
            *(uint4*)&sA[px*SA_STRIDE + cg*4] = t;
        }
        __syncthreads();

        const uint32_t* Ab = sA + (warpM*32 + lq)*SA_STRIDE;
        const uint32_t* Bb = sB + (warpN*96 + lq)*SB_STRIDE;
#pragma unroll
        for (int kb = 0; kb < 8; kb++) {
            int col = kb*8 + 2*lr;
            uint2 a00 = *(const uint2*)&Ab[col];
            uint2 a01 = *(const uint2*)&Ab[8*SA_STRIDE + col];
            uint2 a10 = *(const uint2*)&Ab[16*SA_STRIDE + col];
            uint2 a11 = *(const uint2*)&Ab[24*SA_STRIDE + col];
#pragma unroll
            for (int ni = 0; ni < 12; ni++) {
                uint2 bb = *(const uint2*)&Bb[ni*8*SB_STRIDE + col];
                mma_tf32(acc[0][ni], a00.x, a01.x, a00.y, a01.y, bb.x, bb.y);
                mma_tf32(acc[1][ni], a10.x, a11.x, a10.y, a11.y, bb.x, bb.y);
            }
        }
        __syncthreads();
    }

#pragma unroll
    for (int mi = 0; mi < 2; mi++) {
        int rbase = warpM*32 + mi*16 + lq;
#pragma unroll
        for (int ni = 0; ni < 12; ni++) {
            int cc = warpN*96 + ni*8 + 2*lr;
            *(float2*)&sD[(rbase    )*SD_STRIDE + cc] = make_float2(acc[mi][ni][0], acc[mi][ni][1]);
            *(float2*)&sD[(rbase + 8)*SD_STRIDE + cc] = make_float2(acc[mi][ni][2], acc[mi][ni][3]);
        }
    }
    __syncthreads();

    const float* i2hb = g_i2h + (size_t)b*C3*HW;
#pragma unroll
    for (int it = 0; it < 32; it++) {
        int idx = it*256 + tid;
        int c = idx >> 7, px = idx & 127;
        int p = p0 + px;
        if (p < HW) {
            float hr = sD[px*SD_STRIDE + c      ] + __ldg(&h2h_b[c      ]);
            float hu = sD[px*SD_STRIDE + c +  64] + __ldg(&h2h_b[c +  64]);
            float hm = sD[px*SD_STRIDE + c + 128] + __ldg(&h2h_b[c + 128]);
            float ir = i2hb[(size_t)(c      )*HW + p];
            float iu = i2hb[(size_t)(c +  64)*HW + p];
            float im = i2hb[(size_t)(c + 128)*HW + p];
            float hpv = hp[((size_t)b*HID + c)*HW + p];
            float rg = fsigmoid(ir + hr);
            float ug = fsigmoid(iu + hu);
            float nm = ftanh(im + rg * hm);
            out[((size_t)b*HID + c)*HW + p] = ug * hpv + (1.f - ug) * nm;
        }
    }
}

// ---------------- launch ---------------------------------------------------
extern "C" void kernel_launch(void* const* d_in, const int* in_sizes, int n_in,
                              void* d_out, int out_size)
{
    const float* x       = (const float*)d_in[0];
    const float* h_prev  = (const float*)d_in[1];
    const float* i2h_w   = (const float*)d_in[2];
    const float* i2h_b   = (const float*)d_in[3];
    const float* h2h_w   = (const float*)d_in[4];
    const float* h2h_b   = (const float*)d_in[5];
    const float* i2f_w   = (const float*)d_in[6];
    const float* i2f_b   = (const float*)d_in[7];
    const float* h2f_w   = (const float*)d_in[8];
    const float* h2f_b   = (const float*)d_in[9];
    const float* flows_w = (const float*)d_in[10];
    const float* flows_b = (const float*)d_in[11];
    float* out = (float*)d_out;

    cudaFuncSetAttribute(k_main_mma, cudaFuncAttributeMaxDynamicSharedMemorySize,
                         SMEM_MMA_BYTES);
    cudaFuncSetAttribute(k_f_mma, cudaFuncAttributeMaxDynamicSharedMemorySize,
                         KF_SMEM);
    cudaFuncSetAttribute(k_i2h_mma, cudaFuncAttributeMaxDynamicSharedMemorySize,
                         KI_SMEM);

    dim3 gt(HW/32, HID/32, BATCH);
    k_transpose<<<gt, dim3(32, 8)>>>(h_prev, x);

    k_prep_all<<<(NW_ALL + 255)/256, 256>>>(i2f_w, h2f_w, h2h_w, i2h_w, flows_w);

    dim3 gfm(HH, BATCH);
    k_f_mma<<<gfm, 256, KF_SMEM>>>(i2f_b, h2f_b);
    k_i2h_mma<<<gfm, 256, KI_SMEM>>>(i2h_b);
    k_flows_mma<<<gfm, 256>>>(flows_b);

    dim3 gm((HW + 127)/128, BATCH);
    k_main_mma<<<gm, 256, SMEM_MMA_BYTES>>>(h_prev, h2h_b, out);
}

// round 17
// speedup vs baseline: 1.0643x; 1.0643x over previous
#include <cuda_runtime.h>
#include <math.h>
#include <stdint.h>

#define BATCH 8
#define NCIN 8
#define HID 64
#define LNK 9
#define HH 120
#define WW 120
#define HW (HH*WW)      // 14400
#define C3 (3*HID)      // 192

__device__ __forceinline__ uint32_t f2tf32(float v) {
    uint32_t r; asm("cvt.rna.tf32.f32 %0, %1;" : "=r"(r) : "f"(v)); return r;
}
__device__ __forceinline__ void mma_tf32(float* d,
    uint32_t a0, uint32_t a1, uint32_t a2, uint32_t a3,
    uint32_t b0, uint32_t b1)
{
    asm volatile("mma.sync.aligned.m16n8k8.row.col.f32.tf32.tf32.f32 "
        "{%0,%1,%2,%3}, {%4,%5,%6,%7}, {%8,%9}, {%0,%1,%2,%3};"
        : "+f"(d[0]), "+f"(d[1]), "+f"(d[2]), "+f"(d[3])
        : "r"(a0), "r"(a1), "r"(a2), "r"(a3), "r"(b0), "r"(b1));
}
__device__ __forceinline__ float fsigmoid(float x) {
    return 1.f / (1.f + __expf(-x));
}
__device__ __forceinline__ float ftanh(float x) {
    return 1.f - 2.f / (1.f + __expf(2.f*x));
}
__device__ __forceinline__ int kslot(int k) {
    return (k & ~7) + ((k >> 2) & 1) + 2*(k & 3);
}

// -------- scratch (device globals) ----------------------------------------
__device__ float    g_flows[BATCH*2*LNK*HW];
__device__ float    g_i2h[(size_t)BATCH*C3*HW];
__device__ float4   g_hT4[(size_t)BATCH*HW*16];    // h_prev [b][p][64] fp32 slot-permuted
__device__ uint32_t g_xhT[(size_t)BATCH*HW*72];    // [b][p][72] tf32 permuted
__device__ uint32_t g_fT[(size_t)BATCH*HW*32];     // f [b][p][32] tf32 permuted
__device__ uint32_t g_wf[25*32*72];
__device__ uint32_t g_wB[LNK*192*64];
__device__ uint32_t g_wI[192*72];
__device__ uint32_t g_wFl[25*24*32];

// ---------------- transpose h_prev (+x) -> permuted channels-last ----------
__global__ void k_transpose(const float* __restrict__ hp, const float* __restrict__ x)
{
    __shared__ float t[32][33];
    int b  = blockIdx.z;
    int c0 = blockIdx.y * 32;
    int p0 = blockIdx.x * 32;
    int tx = threadIdx.x, ty = threadIdx.y;
    float* hT = (float*)g_hT4;
#pragma unroll
    for (int k = 0; k < 4; k++) {
        int c = c0 + ty + k*8;
        t[ty + k*8][tx] = hp[((size_t)b*HID + c)*HW + p0 + tx];
    }
    if (blockIdx.y == 0) {
        float vx = x[((size_t)b*NCIN + ty)*HW + p0 + tx];
        g_xhT[((size_t)b*HW + p0 + tx)*72 + kslot(ty)] = f2tf32(vx);
    }
    __syncthreads();
    int c = c0 + tx;
    int slot = kslot(c);
#pragma unroll
    for (int k = 0; k < 4; k++) {
        int p = p0 + ty + k*8;
        float v = t[tx][ty + k*8];
        hT[((size_t)b*HW + p)*HID + slot] = v;
        g_xhT[((size_t)b*HW + p)*72 + 8 + slot] = f2tf32(v);
    }
}

// ---------------- merged weight prep ---------------------------------------
#define NW_F  (25*32*72)
#define NW_B  (LNK*192*64)
#define NW_I  (192*72)
#define NW_FL (25*24*32)
#define NW_ALL (NW_F + NW_B + NW_I + NW_FL)

__global__ void k_prep_all(
    const float* __restrict__ i2f_w, const float* __restrict__ h2f_w,
    const float* __restrict__ h2h_w, const float* __restrict__ i2h_w,
    const float* __restrict__ flows_w)
{
    int idx = blockIdx.x*256 + threadIdx.x;
    if (idx < NW_F) {
        int t  = idx / (32*72);
        int r  = idx % (32*72);
        int oc = r / 72, k = r % 72;
        float v = (k < 8) ? i2f_w[((size_t)oc*NCIN + k)*25 + t]
                          : h2f_w[((size_t)oc*HID + (k-8))*25 + t];
        g_wf[t*(32*72) + oc*72 + kslot(k)] = f2tf32(v);
        return;
    }
    idx -= NW_F;
    if (idx < NW_B) {
        int l = idx / (192*64);
        int r = idx % (192*64);
        int o = r / 64, p = r % 64;
        int k = (p & ~7) + ((p & 1) << 2) + ((p & 7) >> 1);
        g_wB[idx] = f2tf32(h2h_w[(size_t)o*576 + l*64 + k]);
        return;
    }
    idx -= NW_B;
    if (idx < NW_I) {
        int o = idx / 72, p = idx % 72;
        int t = p >> 3, q = p & 7;
        int c = ((q & 1) << 2) + (q >> 1);
        g_wI[idx] = f2tf32(i2h_w[(size_t)o*72 + c*9 + t]);
        return;
    }
    idx -= NW_I;
    if (idx < NW_FL) {
        int t = idx / (24*32);
        int r = idx % (24*32);
        int o = r / 32, p = r % 32;
        int c = (p & ~7) + ((p & 1) << 2) + ((p & 7) >> 1);
        uint32_t v = 0u;
        if (o < 18) v = f2tf32(flows_w[(size_t)o*(32*25) + c*25 + t]);
        g_wFl[t*(24*32) + o*32 + p] = v;
    }
}

// ==========================================================================
// k_f_mma: f = relu(conv5x5(xh; wf)) -> g_fT
// ==========================================================================
#define KF_AS 76
#define KF_AROWS 132
#define KF_OFF_B (KF_AROWS*KF_AS*4)
#define KF_SMEM  (KF_OFF_B + 160*KF_AS*4)

__global__ __launch_bounds__(256, 2) void k_f_mma(
    const float* __restrict__ i2f_b, const float* __restrict__ h2f_b)
{
    extern __shared__ char sm[];
    uint32_t* sA = (uint32_t*)sm;
    uint32_t* sB = (uint32_t*)(sm + KF_OFF_B);

    int b   = blockIdx.y;
    int y0  = blockIdx.x;
    int tid = threadIdx.x;
    int wid = tid >> 5, lane = tid & 31;
    int warpM = wid & 3, warpN = wid >> 2;
    int lq = lane >> 2, lr = lane & 3;

    float acc[2][2][4];
#pragma unroll
    for (int mi = 0; mi < 2; mi++)
#pragma unroll
        for (int ni = 0; ni < 2; ni++)
#pragma unroll
            for (int j = 0; j < 4; j++) acc[mi][ni][j] = 0.f;

    for (int i = tid; i < 8*KF_AS; i += 256)
        sA[124*KF_AS + i] = 0;

    const uint4* xh4 = (const uint4*)(g_xhT + (size_t)b*HW*72);

    for (int dy = 0; dy < 5; dy++) {
        __syncthreads();
        int iy = y0 + dy - 2;
        for (int idx = tid; idx < 124*18; idx += 256) {
            int col = idx / 18, kq = idx % 18;
            int gx = col - 2;
            uint4 v = make_uint4(0u, 0u, 0u, 0u);
            if (iy >= 0 && iy < HH && gx >= 0 && gx < WW)
                v = xh4[((size_t)iy*WW + gx)*18 + kq];
            *(uint4*)&sA[col*KF_AS + kq*4] = v;
        }
        const uint4* wsrc = (const uint4*)&g_wf[dy*5*(32*72)];
        for (int idx = tid; idx < 5*32*18; idx += 256) {
            int row = idx / 18, kq = idx % 18;
            *(uint4*)&sB[row*KF_AS + kq*4] = wsrc[row*18 + kq];
        }
        __syncthreads();

#pragma unroll
        for (int dx = 0; dx < 5; dx++) {
            const uint32_t* Ab = sA + (warpM*32 + dx + lq)*KF_AS;
            const uint32_t* Bb = sB + (dx*32 + warpN*16 + lq)*KF_AS;
#pragma unroll
            for (int kb = 0; kb < 9; kb++) {
                int col = kb*8 + 2*lr;
                uint2 a00 = *(const uint2*)&Ab[col];
                uint2 a01 = *(const uint2*)&Ab[ 8*KF_AS + col];
                uint2 a10 = *(const uint2*)&Ab[16*KF_AS + col];
                uint2 a11 = *(const uint2*)&Ab[24*KF_AS + col];
                uint2 b0  = *(const uint2*)&Bb[col];
                uint2 b1  = *(const uint2*)&Bb[ 8*KF_AS + col];
                mma_tf32(acc[0][0], a00.x, a01.x, a00.y, a01.y, b0.x, b0.y);
                mma_tf32(acc[0][1], a00.x, a01.x, a00.y, a01.y, b1.x, b1.y);
                mma_tf32(acc[1][0], a10.x, a11.x, a10.y, a11.y, b0.x, b0.y);
                mma_tf32(acc[1][1], a10.x, a11.x, a10.y, a11.y, b1.x, b1.y);
            }
        }
    }

    __syncthreads();
#pragma unroll
    for (int ni = 0; ni < 2; ni++) {
        int ocA = warpN*16 + ni*8 + 2*lr, ocB = ocA + 1;
        int sA_ = kslot(ocA), sB_ = kslot(ocB);
        float bA = __ldg(&i2f_b[ocA]) + __ldg(&h2f_b[ocA]);
        float bB = __ldg(&i2f_b[ocB]) + __ldg(&h2f_b[ocB]);
#pragma unroll
        for (int mi = 0; mi < 2; mi++) {
            int x0 = warpM*32 + mi*16 + lq;
            int x1 = x0 + 8;
            sA[x0*32 + sA_] = f2tf32(fmaxf(acc[mi][ni][0] + bA, 0.f));
            sA[x0*32 + sB_] = f2tf32(fmaxf(acc[mi][ni][1] + bB, 0.f));
            sA[x1*32 + sA_] = f2tf32(fmaxf(acc[mi][ni][2] + bA, 0.f));
            sA[x1*32 + sB_] = f2tf32(fmaxf(acc[mi][ni][3] + bB, 0.f));
        }
    }
    __syncthreads();
    uint4* fT4 = (uint4*)(g_fT + ((size_t)b*HW + (size_t)y0*WW)*32);
    for (int idx = tid; idx < 120*8; idx += 256)
        fT4[idx] = ((const uint4*)sA)[idx];
}

// ==========================================================================
// k_flows_mma: flows = conv5x5(f; wFl)
// ==========================================================================
#define KFL_AS 36
__global__ __launch_bounds__(256, 2) void k_flows_mma(const float* __restrict__ flows_b)
{
    __shared__ uint32_t sA[KF_AROWS*KFL_AS];
    __shared__ uint32_t sB[120*KFL_AS];

    int b   = blockIdx.y;
    int y0  = blockIdx.x;
    int tid = threadIdx.x;
    int wid = tid >> 5, lane = tid & 31;
    int lq = lane >> 2, lr = lane & 3;

    float acc[3][4];
#pragma unroll
    for (int ni = 0; ni < 3; ni++)
#pragma unroll
        for (int j = 0; j < 4; j++) acc[ni][j] = 0.f;

    for (int i = tid; i < 8*KFL_AS; i += 256)
        sA[124*KFL_AS + i] = 0;

    const uint4* fT4 = (const uint4*)(g_fT + (size_t)b*HW*32);

    for (int dy = 0; dy < 5; dy++) {
        __syncthreads();
        int iy = y0 + dy - 2;
        for (int idx = tid; idx < 124*8; idx += 256) {
            int col = idx >> 3, kq = idx & 7;
            int gx = col - 2;
            uint4 v = make_uint4(0u, 0u, 0u, 0u);
            if (iy >= 0 && iy < HH && gx >= 0 && gx < WW)
                v = fT4[((size_t)iy*WW + gx)*8 + kq];
            *(uint4*)&sA[col*KFL_AS + kq*4] = v;
        }
        const uint4* wsrc = (const uint4*)&g_wFl[dy*5*(24*32)];
        for (int idx = tid; idx < 5*24*8; idx += 256) {
            int row = idx >> 3, kq = idx & 7;
            *(uint4*)&sB[row*KFL_AS + kq*4] = wsrc[idx];
        }
        __syncthreads();

#pragma unroll
        for (int dx = 0; dx < 5; dx++) {
            const uint32_t* Ab = sA + (wid*16 + dx + lq)*KFL_AS;
            const uint32_t* Bb = sB + (dx*24 + lq)*KFL_AS;
#pragma unroll
            for (int kb = 0; kb < 4; kb++) {
                int col = kb*8 + 2*lr;
                uint2 a0 = *(const uint2*)&Ab[col];
                uint2 a1 = *(const uint2*)&Ab[8*KFL_AS + col];
#pragma unroll
                for (int ni = 0; ni < 3; ni++) {
                    uint2 bb = *(const uint2*)&Bb[ni*8*KFL_AS + col];
                    mma_tf32(acc[ni], a0.x, a1.x, a0.y, a1.y, bb.x, bb.y);
                }
            }
        }
    }

    int x0 = wid*16 + lq, x1 = x0 + 8;
#pragma unroll
    for (int ni = 0; ni < 3; ni++) {
        int ocA = ni*8 + 2*lr, ocB = ocA + 1;
        if (ocA < 18) {
            float bias = __ldg(&flows_b[ocA]);
            float* o = &g_flows[((size_t)b*(2*LNK) + ocA)*HW + (size_t)y0*WW];
            if (x0 < WW) o[x0] = acc[ni][0] + bias;
            if (x1 < WW) o[x1] = acc[ni][2] + bias;
        }
        if (ocB < 18) {
            float bias = __ldg(&flows_b[ocB]);
            float* o = &g_flows[((size_t)b*(2*LNK) + ocB)*HW + (size_t)y0*WW];
            if (x0 < WW) o[x0] = acc[ni][1] + bias;
            if (x1 < WW) o[x1] = acc[ni][3] + bias;
        }
    }
}

// ==========================================================================
// k_i2h_mma: i2h = conv3x3(x) full 192 oc, NCHW out
// ==========================================================================
#define KI_AS 76
#define KI_OFF_B (128*KI_AS*4)
#define KI_SMEM  (KI_OFF_B + 192*KI_AS*4)

__global__ __launch_bounds__(256, 2) void k_i2h_mma(const float* __restrict__ i2h_b)
{
    extern __shared__ char sm[];
    uint32_t* sA = (uint32_t*)sm;
    uint32_t* sB = (uint32_t*)(sm + KI_OFF_B);

    int b   = blockIdx.y;
    int y0  = blockIdx.x;
    int tid = threadIdx.x;
    int wid = tid >> 5, lane = tid & 31;
    int warpM = wid & 3, warpN = wid >> 2;
    int lq = lane >> 2, lr = lane & 3;

    const uint4* xh4 = (const uint4*)(g_xhT + (size_t)b*HW*72);

    for (int idx = tid; idx < 128*18; idx += 256) {
        int px = idx / 18, r = idx % 18;
        int t = r >> 1, half = r & 1;
        int dy = t / 3, dx = t % 3;
        int iy = y0 + dy - 1, gx = px + dx - 1;
        uint4 v = make_uint4(0u, 0u, 0u, 0u);
        if (iy >= 0 && iy < HH && gx >= 0 && gx < WW)
            v = xh4[((size_t)iy*WW + gx)*18 + half];
        *(uint4*)&sA[px*KI_AS + t*8 + half*4] = v;
    }
    {
        const uint4* wI4 = (const uint4*)g_wI;
        for (int idx = tid; idx < 192*18; idx += 256) {
            int o = idx / 18, kq = idx % 18;
            *(uint4*)&sB[o*KI_AS + kq*4] = wI4[idx];
        }
    }
    __syncthreads();

    float acc[2][12][4];
#pragma unroll
    for (int mi = 0; mi < 2; mi++)
#pragma unroll
        for (int ni = 0; ni < 12; ni++)
#pragma unroll
            for (int j = 0; j < 4; j++) acc[mi][ni][j] = 0.f;

    const uint32_t* Ab = sA + (warpM*32 + lq)*KI_AS;
    const uint32_t* Bb = sB + (warpN*96 + lq)*KI_AS;
#pragma unroll
    for (int kb = 0; kb < 9; kb++) {
        int col = kb*8 + 2*lr;
        uint2 a00 = *(const uint2*)&Ab[col];
        uint2 a01 = *(const uint2*)&Ab[ 8*KI_AS + col];
        uint2 a10 = *(const uint2*)&Ab[16*KI_AS + col];
        uint2 a11 = *(const uint2*)&Ab[24*KI_AS + col];
#pragma unroll
        for (int ni = 0; ni < 12; ni++) {
            uint2 bb = *(const uint2*)&Bb[ni*8*KI_AS + col];
            mma_tf32(acc[0][ni], a00.x, a01.x, a00.y, a01.y, bb.x, bb.y);
            mma_tf32(acc[1][ni], a10.x, a11.x, a10.y, a11.y, bb.x, bb.y);
        }
    }

#pragma unroll
    for (int ni = 0; ni < 12; ni++) {
        int ocA = warpN*96 + ni*8 + 2*lr, ocB = ocA + 1;
        float bA = __ldg(&i2h_b[ocA]);
        float bB = __ldg(&i2h_b[ocB]);
        float* oA = &g_i2h[((size_t)b*C3 + ocA)*HW + (size_t)y0*WW];
        float* oB = &g_i2h[((size_t)b*C3 + ocB)*HW + (size_t)y0*WW];
#pragma unroll
        for (int mi = 0; mi < 2; mi++) {
            int x0 = warpM*32 + mi*16 + lq;
            int x1 = x0 + 8;
            if (x0 < WW) {
                oA[x0] = acc[mi][ni][0] + bA;
                oB[x0] = acc[mi][ni][1] + bB;
            }
            if (x1 < WW) {
                oA[x1] = acc[mi][ni][2] + bA;
                oB[x1] = acc[mi][ni][3] + bB;
            }
        }
    }
}

// ==========================================================================
// k_main: warp(x9) + 1x1 conv + GRU gates (R10 measured-best structure)
// ==========================================================================
#define SA_STRIDE 72
#define SB_STRIDE 72
#define OFF_GEO 0
#define OFF_A   4096
#define OFF_B   (OFF_A + 128*SA_STRIDE*4)
#define PHASE1_BYTES (OFF_B + 192*SB_STRIDE*4)
#define SD_STRIDE 194
#define SD_BYTES (128*SD_STRIDE*4)
#define SMEM_MMA_BYTES (SD_BYTES > PHASE1_BYTES ? SD_BYTES : PHASE1_BYTES)

__global__ __launch_bounds__(256, 2) void k_main_mma(
    const float* __restrict__ hp,
    const float* __restrict__ h2h_b,
    float* __restrict__ out)
{
    extern __shared__ char sm[];
    float*    sgeo = (float*)(sm + OFF_GEO);
    uint32_t* sA   = (uint32_t*)(sm + OFF_A);
    uint32_t* sB   = (uint32_t*)(sm + OFF_B);
    float*    sD   = (float*)sm;

    int b   = blockIdx.y;
    int p0  = blockIdx.x * 128;
    int tid = threadIdx.x;
    int wid = tid >> 5, lane = tid & 31;
    int warpM = wid & 3, warpN = wid >> 2;
    int lq = lane >> 2, lr = lane & 3;

    float acc[2][12][4];
#pragma unroll
    for (int mi = 0; mi < 2; mi++)
#pragma unroll
        for (int ni = 0; ni < 12; ni++)
#pragma unroll
            for (int j = 0; j < 4; j++) acc[mi][ni][j] = 0.f;

    const float4* hT4 = g_hT4 + (size_t)b*HW*16;

    for (int l = 0; l < LNK; l++) {
        if (tid < 128) {
            int p = p0 + tid; if (p > HW-1) p = HW-1;
            int yc = p / WW, xc = p - yc*WW;
            float sx = (float)xc + g_flows[((size_t)b*(2*LNK) + 2*l    )*HW + p];
            float sy = (float)yc + g_flows[((size_t)b*(2*LNK) + 2*l + 1)*HW + p];
            float fx = floorf(sx), fy = floorf(sy);
            float wx1 = sx - fx, wy1 = sy - fy;
            float wx0 = 1.f - wx1, wy0 = 1.f - wy1;
            int ix0 = (int)fx, iy0 = (int)fy;
            bool vx0 = (ix0 >= 0) && (ix0 < WW);
            bool vx1 = (ix0 >= -1) && (ix0 < WW - 1);
            bool vy0 = (iy0 >= 0) && (iy0 < HH);
            bool vy1 = (iy0 >= -1) && (iy0 < HH - 1);
            int r0 = iy0*WW, r1 = r0 + WW;
            float* g = &sgeo[tid*8];
            g[0] = wy0*wx0; g[1] = wy0*wx1; g[2] = wy1*wx0; g[3] = wy1*wx1;
            ((int*)g)[4] = (vy0 && vx0) ? (r0 + ix0)     : -1;
            ((int*)g)[5] = (vy0 && vx1) ? (r0 + ix0 + 1) : -1;
            ((int*)g)[6] = (vy1 && vx0) ? (r1 + ix0)     : -1;
            ((int*)g)[7] = (vy1 && vx1) ? (r1 + ix0 + 1) : -1;
        }
        __syncthreads();

        {
            const uint4* wB4 = (const uint4*)&g_wB[(size_t)l*192*64];
#pragma unroll
            for (int i = 0; i < 12; i++) {
                int q = i*256 + tid;
                int o = q >> 4, kq = q & 15;
                *(uint4*)&sB[o*SB_STRIDE + kq*4] = wB4[o*16 + kq];
            }
        }

#pragma unroll
        for (int i = 0; i < 8; i++) {
            int item = i*256 + tid;
            int px = item >> 4, cg = item & 15;
            const float* g = &sgeo[px*8];
            float w00 = g[0], w01 = g[1], w10 = g[2], w11 = g[3];
            int i00 = ((const int*)g)[4], i01 = ((const int*)g)[5];
            int i10 = ((const int*)g)[6], i11 = ((const int*)g)[7];
            float ax=0.f, ay=0.f, az=0.f, aw=0.f;
            if (i00 >= 0) { float4 v = hT4[(size_t)i00*16 + cg];
                ax += w00*v.x; ay += w00*v.y; az += w00*v.z; aw += w00*v.w; }
            if (i01 >= 0) { float4 v = hT4[(size_t)i01*16 + cg];
                ax += w01*v.x; ay += w01*v.y; az += w01*v.z; aw += w01*v.w; }
            if (i10 >= 0) { float4 v = hT4[(size_t)i10*16 + cg];
                ax += w10*v.x; ay += w10*v.y; az += w10*v.z; aw += w10*v.w; }
            if (i11 >= 0) { float4 v = hT4[(size_t)i11*16 + cg];
                ax += w11*v.x; ay += w11*v.y; az += w11*v.z; aw += w11*v.w; }
            uint4 t;
            t.x = f2tf32(ax); t.y = f2tf32(ay); t.z = f2tf32(az); t.w = f2tf32(aw);
            *(uint4*)&sA[px*SA_STRIDE + cg*4] = t;
        }
        __syncthreads();

        const uint32_t* Ab = sA + (warpM*32 + lq)*SA_STRIDE;
        const uint32_t* Bb = sB + (warpN*96 + lq)*SB_STRIDE;
#pragma unroll
        for (int kb = 0; kb < 8; kb++) {
            int col = kb*8 + 2*lr;
            uint2 a00 = *(const uint2*)&Ab[col];
            uint2 a01 = *(const uint2*)&Ab[8*SA_STRIDE + col];
            uint2 a10 = *(const uint2*)&Ab[16*SA_STRIDE + col];
            uint2 a11 = *(const uint2*)&Ab[24*SA_STRIDE + col];
#pragma unroll
            for (int ni = 0; ni < 12; ni++) {
                uint2 bb = *(const uint2*)&Bb[ni*8*SB_STRIDE + col];
                mma_tf32(acc[0][ni], a00.x, a01.x, a00.y, a01.y, bb.x, bb.y);
                mma_tf32(acc[1][ni], a10.x, a11.x, a10.y, a11.y, bb.x, bb.y);
            }
        }
        __syncthreads();
    }

#pragma unroll
    for (int mi = 0; mi < 2; mi++) {
        int rbase = warpM*32 + mi*16 + lq;
#pragma unroll
        for (int ni = 0; ni < 12; ni++) {
            int cc = warpN*96 + ni*8 + 2*lr;
            *(float2*)&sD[(rbase    )*SD_STRIDE + cc] = make_float2(acc[mi][ni][0], acc[mi][ni][1]);
            *(float2*)&sD[(rbase + 8)*SD_STRIDE + cc] = make_float2(acc[mi][ni][2], acc[mi][ni][3]);
        }
    }
    __syncthreads();

    const float* i2hb = g_i2h + (size_t)b*C3*HW;
#pragma unroll
    for (int it = 0; it < 32; it++) {
        int idx = it*256 + tid;
        int c = idx >> 7, px = idx & 127;
        int p = p0 + px;
        if (p < HW) {
            float hr = sD[px*SD_STRIDE + c      ] + __ldg(&h2h_b[c      ]);
            float hu = sD[px*SD_STRIDE + c +  64] + __ldg(&h2h_b[c +  64]);
            float hm = sD[px*SD_STRIDE + c + 128] + __ldg(&h2h_b[c + 128]);
            float ir = i2hb[(size_t)(c      )*HW + p];
            float iu = i2hb[(size_t)(c +  64)*HW + p];
            float im = i2hb[(size_t)(c + 128)*HW + p];
            float hpv = hp[((size_t)b*HID + c)*HW + p];
            float rg = fsigmoid(ir + hr);
            float ug = fsigmoid(iu + hu);
            float nm = ftanh(im + rg * hm);
            out[((size_t)b*HID + c)*HW + p] = ug * hpv + (1.f - ug) * nm;
        }
    }
}

// ---------------- launch ---------------------------------------------------
extern "C" void kernel_launch(void* const* d_in, const int* in_sizes, int n_in,
                              void* d_out, int out_size)
{
    const float* x       = (const float*)d_in[0];
    const float* h_prev  = (const float*)d_in[1];
    const float* i2h_w   = (const float*)d_in[2];
    const float* i2h_b   = (const float*)d_in[3];
    const float* h2h_w   = (const float*)d_in[4];
    const float* h2h_b   = (const float*)d_in[5];
    const float* i2f_w   = (const float*)d_in[6];
    const float* i2f_b   = (const float*)d_in[7];
    const float* h2f_w   = (const float*)d_in[8];
    const float* h2f_b   = (const float*)d_in[9];
    const float* flows_w = (const float*)d_in[10];
    const float* flows_b = (const float*)d_in[11];
    float* out = (float*)d_out;

    cudaFuncSetAttribute(k_main_mma, cudaFuncAttributeMaxDynamicSharedMemorySize,
                         SMEM_MMA_BYTES);
    cudaFuncSetAttribute(k_f_mma, cudaFuncAttributeMaxDynamicSharedMemorySize,
                         KF_SMEM);
    cudaFuncSetAttribute(k_i2h_mma, cudaFuncAttributeMaxDynamicSharedMemorySize,
                         KI_SMEM);

    dim3 gt(HW/32, HID/32, BATCH);
    k_transpose<<<gt, dim3(32, 8)>>>(h_prev, x);

    k_prep_all<<<(NW_ALL + 255)/256, 256>>>(i2f_w, h2f_w, h2h_w, i2h_w, flows_w);

    dim3 gfm(HH, BATCH);
    k_f_mma<<<gfm, 256, KF_SMEM>>>(i2f_b, h2f_b);
    k_i2h_mma<<<gfm, 256, KI_SMEM>>>(i2h_b);
    k_flows_mma<<<gfm, 256>>>(flows_b);

    dim3 gm((HW + 127)/128, BATCH);
    k_main_mma<<<gm, 256, SMEM_MMA_BYTES>>>(h_prev, h2h_b, out);
}